// round 7
// baseline (speedup 1.0000x reference)
#include <cuda_runtime.h>
#include <cstddef>

#define L_SEQ 512
#define B_SZ  64
#define D_IN  512
#define HALFH 256
#define G4    1024                 // 4*HALF gate rows per direction
#define M_TOT (L_SEQ * B_SZ)      // 32768
#define NBPD  64                  // blocks per direction in recurrence
#define HB    4                   // hidden units per block

typedef unsigned long long u64;

// ---------------------------------------------------------------------------
// Packed fp32x2 helpers (sm_100+). IEEE fp32 per lane -> bit-identical math.
// ---------------------------------------------------------------------------
__device__ __forceinline__ u64 f2_pack(float lo, float hi) {
    u64 r; asm("mov.b64 %0, {%1, %2};" : "=l"(r) : "f"(lo), "f"(hi)); return r;
}
__device__ __forceinline__ u64 f2_dup(float v) {
    u64 r; asm("mov.b64 %0, {%1, %1};" : "=l"(r) : "f"(v)); return r;
}
__device__ __forceinline__ void f2_unpack(u64 p, float& lo, float& hi) {
    asm("mov.b64 {%0, %1}, %2;" : "=f"(lo), "=f"(hi) : "l"(p));
}
__device__ __forceinline__ u64 f2_fma(u64 a, u64 b, u64 c) {
    u64 d; asm("fma.rn.f32x2 %0, %1, %2, %3;" : "=l"(d) : "l"(a), "l"(b), "l"(c));
    return d;
}

// Scratch: xw[dir][g][m] with m = l*B + b   (256 MB, module-static: allowed)
__device__ float g_xw[(size_t)2 * G4 * M_TOT];
// Double-buffered hidden state: [dir][buf][b][k]
__device__ float g_h[2][2][B_SZ][HALFH];
// Grid barrier state per direction (cnt returns to 0 each phase; gen monotonic)
__device__ unsigned g_cnt[2];
__device__ unsigned g_gen[2];

// ---------------------------------------------------------------------------
// Kernel 1: xw[dir][g][m] = sum_d W_ih[g][d] * x[m][d] + b_ih[g] + b_hh[g]
// Tiles: 64(g) x 64(m) x 16(k), 256 threads, 4x4 register tile, FFMA2 math.
// fma-pipe bound (512 cyc/stage vs 448 issue slots); ~5 CTAs/SM hide LDG.
// ---------------------------------------------------------------------------
__global__ __launch_bounds__(256) void gemm_xw_kernel(
    const float* __restrict__ x,
    const float* __restrict__ Wf, const float* __restrict__ Wb,
    const float* __restrict__ bihf, const float* __restrict__ bhhf,
    const float* __restrict__ bihb, const float* __restrict__ bhhb)
{
    const int dir = blockIdx.z;
    const float* __restrict__ W   = dir ? Wb   : Wf;
    const float* __restrict__ bih = dir ? bihb : bihf;
    const float* __restrict__ bhh = dir ? bhhb : bhhf;

    const int m0 = blockIdx.x * 64;
    const int g0 = blockIdx.y * 64;

    __shared__ float As[16][68];   // As[k][g']  (transposed stage; 272B row = 16B-aligned)
    __shared__ float Bs[16][68];   // Bs[k][m']

    const int tid = threadIdx.x;
    const int tx  = tid & 15;      // m sub-tile
    const int ty  = tid >> 4;      // g sub-tile

    const int lrow = tid >> 2;          // 0..63 (tile row to load)
    const int lc   = (tid & 3) * 4;     // k offset 0,4,8,12

    const float* Arow = W + (size_t)(g0 + lrow) * D_IN + lc;
    const float* Brow = x + (size_t)(m0 + lrow) * D_IN + lc;

    // acc2[i][0] = (acc[i][0], acc[i][1]); acc2[i][1] = (acc[i][2], acc[i][3])
    u64 acc2[4][2] = {};

    for (int k0 = 0; k0 < D_IN; k0 += 16) {
        float4 av = *(const float4*)(Arow + k0);
        float4 bv = *(const float4*)(Brow + k0);
        __syncthreads();
        As[lc + 0][lrow] = av.x; As[lc + 1][lrow] = av.y;
        As[lc + 2][lrow] = av.z; As[lc + 3][lrow] = av.w;
        Bs[lc + 0][lrow] = bv.x; Bs[lc + 1][lrow] = bv.y;
        Bs[lc + 2][lrow] = bv.z; Bs[lc + 3][lrow] = bv.w;
        __syncthreads();
#pragma unroll
        for (int kk = 0; kk < 16; kk++) {
            float4     a  = *(const float4*)&As[kk][ty * 4];     // warp-broadcast
            ulonglong2 bp = *(const ulonglong2*)&Bs[kk][tx * 4]; // conflict-free phases
            u64 d0 = f2_dup(a.x), d1 = f2_dup(a.y),
                d2 = f2_dup(a.z), d3 = f2_dup(a.w);
            acc2[0][0] = f2_fma(d0, bp.x, acc2[0][0]);
            acc2[0][1] = f2_fma(d0, bp.y, acc2[0][1]);
            acc2[1][0] = f2_fma(d1, bp.x, acc2[1][0]);
            acc2[1][1] = f2_fma(d1, bp.y, acc2[1][1]);
            acc2[2][0] = f2_fma(d2, bp.x, acc2[2][0]);
            acc2[2][1] = f2_fma(d2, bp.y, acc2[2][1]);
            acc2[3][0] = f2_fma(d3, bp.x, acc2[3][0]);
            acc2[3][1] = f2_fma(d3, bp.y, acc2[3][1]);
        }
    }

#pragma unroll
    for (int i = 0; i < 4; i++) {
        int g = g0 + ty * 4 + i;
        float bb = bih[g] + bhh[g];
        float c0, c1, c2, c3;
        f2_unpack(acc2[i][0], c0, c1);
        f2_unpack(acc2[i][1], c2, c3);
        float4 o;
        o.x = c0 + bb; o.y = c1 + bb; o.z = c2 + bb; o.w = c3 + bb;
        size_t base = ((size_t)dir * G4 + g) * M_TOT + m0 + tx * 4;
        *(float4*)&g_xw[base] = o;
    }
}

// ---------------------------------------------------------------------------
// Grid barrier over the NBPD blocks of one direction.
// bar.sync (cta-scope ordering of all threads' writes) -> tid0 fence.gpu
// (cumulative: covers the whole block's writes; the acquire fence after the
// spin emits CCTL.IVALL, flushing this SM's non-coherent L1D before any
// thread re-reads g_h) -> atomic arrive/release.
// ---------------------------------------------------------------------------
__device__ __forceinline__ void grid_barrier(int dir)
{
    __syncthreads();
    if (threadIdx.x == 0) {
        volatile unsigned* vgen = &g_gen[dir];
        unsigned g = *vgen;                  // read BEFORE arriving: still this phase
        __threadfence();                     // publish our h writes (cumulative)
        unsigned old = atomicAdd(&g_cnt[dir], 1u);
        if (old == NBPD - 1) {
            atomicExch(&g_cnt[dir], 0u);
            __threadfence();
            atomicAdd(&g_gen[dir], 1u);      // release
        } else {
            while (*vgen == g) { }           // spin (volatile -> L2)
        }
        __threadfence();                     // acquire (L1D invalidate)
    }
    __syncthreads();
}

// ---------------------------------------------------------------------------
// Kernel 2: persistent bidirectional LSTM recurrence.
// Grid = 128 blocks (0..63 fwd, 64..127 bwd), 256 threads each.
// 128 blocks <= 148 SMs -> whole grid co-resident in wave 1 (no deadlock).
// Block owns HB=4 hidden units. Thread (b, q) computes ALL FOUR gates of its
// own cell (b, j0+q): no gate exchange, no second syncthreads.
// W_p PAIR-INTERLEAVED per hidden unit ((i,f) pair / (g,o) pair) so one
// LDS.128 yields two u64 FFMA2 operands.
// xw seeds are DRAM-resident (256 MB scratch): accumulate from ZERO and add
// seeds AFTER the dot loop, so the 577-cyc seed LDGs hide under ~2200 cyc of
// compute instead of racing the staging phase.
// h staging: 16 LDG.128 front-batched into registers (MLP_eff = 16), then
// 16 STS.128 -- guarantees full L2 latency overlap every step.
// Dynamic SMEM: h_s[64][260] + W_p[8][520] = 83200 B (1 CTA/SM)
// ---------------------------------------------------------------------------
__global__ __launch_bounds__(256, 1) void lstm_rec_kernel(
    const float* __restrict__ mask,
    const float* __restrict__ Whhf, const float* __restrict__ Whhb,
    float* __restrict__ out)
{
    extern __shared__ float smem[];
    float (*h_s)[260] = (float(*)[260])smem;                     // 64 x 260
    float (*W_p)[520] = (float(*)[520])(smem + 64 * 260);        // 8  x 520

    const int blk = blockIdx.x;
    const int dir = blk >> 6;
    const int j0  = (blk & 63) * HB;
    const float* __restrict__ Whh = dir ? Whhb : Whhf;

    const int tid = threadIdx.x;
    const int b   = tid & 63;     // batch lane
    const int q   = tid >> 6;     // local hidden unit owned by this thread

    // Load W slice pair-interleaved BY HIDDEN UNIT:
    //   local row r = jj*4 + gt  <-  Whh[gt*HALF + j0 + jj][:]
    //   pair pr = jj*2 + (gt>>1), slot = gt&1;  W_p[pr][2*k + slot] = row[k]
    for (int idx = tid; idx < 16 * 64; idx += 256) {
        int r = idx >> 6, kq = idx & 63;
        int jj = r >> 2, gt = r & 3;
        float4 w4 = *(const float4*)&Whh[(size_t)(gt * HALFH + j0 + jj) * HALFH + kq * 4];
        int pr = jj * 2 + (gt >> 1), slot = gt & 1, kb = kq * 4;
        W_p[pr][2 * (kb + 0) + slot] = w4.x;
        W_p[pr][2 * (kb + 1) + slot] = w4.y;
        W_p[pr][2 * (kb + 2) + slot] = w4.z;
        W_p[pr][2 * (kb + 3) + slot] = w4.w;
    }

    // Zero our slice of the step-0 read buffer; c lives in a register.
    g_h[dir][0][b][j0 + q] = 0.0f;
    float c = 0.0f;

    grid_barrier(dir);   // includes the fences; zeros visible to all blocks

    const float* __restrict__ WpIF = &W_p[2 * q + 0][0];   // gates (i,f) of unit j0+q
    const float* __restrict__ WpGO = &W_p[2 * q + 1][0];   // gates (g,o) of unit j0+q

    // Strength-reduced stream pointers (stride +/-B_SZ per step).
    const int t0 = dir ? (L_SEQ - 1) : 0;
    const ptrdiff_t dstep = dir ? -(ptrdiff_t)B_SZ : (ptrdiff_t)B_SZ;
    const float* __restrict__ xwb =
        g_xw + (size_t)dir * G4 * M_TOT + (size_t)t0 * B_SZ + b;
    const float* pi = xwb + (size_t)(0 * HALFH + j0 + q) * M_TOT;
    const float* pf = xwb + (size_t)(1 * HALFH + j0 + q) * M_TOT;
    const float* pg = xwb + (size_t)(2 * HALFH + j0 + q) * M_TOT;
    const float* po = xwb + (size_t)(3 * HALFH + j0 + q) * M_TOT;
    const float* pm = mask + (size_t)t0 * B_SZ + b;
    float* pout = out + ((size_t)t0 * B_SZ + b) * 512 + dir * HALFH + j0 + q;
    const ptrdiff_t dout = dstep * 512;

    // Staging: thread tid covers rows bb = tid>>6 + {0,4,...,60} at column
    // block kq = (tid & 63); one float4 per row -> 16 LDG.128 + 16 STS.128.
    const int st_b0 = tid >> 6;          // 0..3
    const int st_kq = (tid & 63) * 4;    // 0..252
    const float* hsrc0 = &g_h[dir][0][0][0] + (size_t)st_b0 * HALFH + st_kq;
    const size_t hbufoff = (size_t)B_SZ * HALFH;   // floats between buf0/buf1
    float* hdst0 = &g_h[dir][1][0][0] + (size_t)b * HALFH + j0 + q; // write ptr base
    float* hwr[2] = { hdst0 - hbufoff + 0, hdst0 }; // [to-buf0 is -off].. see below

    int rbuf = 0;

    for (int s = 0; s < L_SEQ; s++) {
        // Issue seed + mask LDGs early; consumed only AFTER the dot loop.
        float ai = *pi, af = *pf, ag = *pg, ao = *po;
        float mv = *pm;

        // Stage full h (64x256): front-batch all 16 LDG.128, then 16 STS.128.
        {
            const float* src = hsrc0 + (size_t)rbuf * hbufoff;
            float4 r[16];
#pragma unroll
            for (int i = 0; i < 16; i++)
                r[i] = *(const float4*)(src + (size_t)(i * 4) * HALFH);
#pragma unroll
            for (int i = 0; i < 16; i++)
                *(float4*)&h_s[st_b0 + i * 4][st_kq] = r[i];
        }
        __syncthreads();

        u64 accIF = 0;   // packed (0.0f, 0.0f)
        u64 accGO = 0;

        // gates(i,f,g,o)[b, j0+q] += sum_k h[b][k] * W[row][k]
        // Per 4 k: 1 h LDS.128 (conflict-free: stride 260 = 4 mod 32) +
        //          4 W LDS.128 (warp-broadcast) + 4 dup movs + 8 FFMA2
#pragma unroll 8
        for (int k = 0; k < HALFH; k += 4) {
            float4 h4 = *(const float4*)&h_s[b][k];
            ulonglong2 wi0 = *(const ulonglong2*)&WpIF[2 * k];     // k, k+1 (i,f) pairs
            ulonglong2 wi1 = *(const ulonglong2*)&WpIF[2 * k + 4]; // k+2, k+3
            ulonglong2 wg0 = *(const ulonglong2*)&WpGO[2 * k];
            ulonglong2 wg1 = *(const ulonglong2*)&WpGO[2 * k + 4];
            u64 hx = f2_dup(h4.x), hy = f2_dup(h4.y),
                hz = f2_dup(h4.z), hw = f2_dup(h4.w);
            accIF = f2_fma(hx, wi0.x, accIF);
            accIF = f2_fma(hy, wi0.y, accIF);
            accIF = f2_fma(hz, wi1.x, accIF);
            accIF = f2_fma(hw, wi1.y, accIF);
            accGO = f2_fma(hx, wg0.x, accGO);
            accGO = f2_fma(hy, wg0.y, accGO);
            accGO = f2_fma(hz, wg1.x, accGO);
            accGO = f2_fma(hw, wg1.y, accGO);
        }

        // Cell update: add seeds now (their DRAM latency is long hidden).
        float di, df, dg, dgo;
        f2_unpack(accIF, di, df);
        f2_unpack(accGO, dg, dgo);
        float gi = di + ai, gf = df + af, gg = dg + ag, go = dgo + ao;
        float si = 1.0f / (1.0f + __expf(-gi));
        float sf = 1.0f / (1.0f + __expf(-gf));
        float so = 1.0f / (1.0f + __expf(-go));
        c = sf * c + si * tanhf(gg);
        float h = so * tanhf(c);
        h *= mv;
        c *= mv;

        hwr[rbuf ^ 1][0] = h;   // write to the other buffer
        *pout = h;

        grid_barrier(dir);   // fences h writes; all blocks step together
        rbuf ^= 1;
        pi += dstep; pf += dstep; pg += dstep; po += dstep;
        pm += dstep; pout += dout;
    }
}

// ---------------------------------------------------------------------------
// Launch
// d_in: 0=x 1=mask 2=W_ih_f 3=W_hh_f 4=b_ih_f 5=b_hh_f 6=W_ih_b 7=W_hh_b 8=b_ih_b 9=b_hh_b
// ---------------------------------------------------------------------------
extern "C" void kernel_launch(void* const* d_in, const int* in_sizes, int n_in,
                              void* d_out, int out_size)
{
    const float* x     = (const float*)d_in[0];
    const float* mask  = (const float*)d_in[1];
    const float* Wihf  = (const float*)d_in[2];
    const float* Whhf  = (const float*)d_in[3];
    const float* bihf  = (const float*)d_in[4];
    const float* bhhf  = (const float*)d_in[5];
    const float* Wihb  = (const float*)d_in[6];
    const float* Whhb  = (const float*)d_in[7];
    const float* bihb  = (const float*)d_in[8];
    const float* bhhb  = (const float*)d_in[9];
    float* out = (float*)d_out;

    // Idempotent, deterministic; needed for 83 KB dynamic SMEM.
    cudaFuncSetAttribute(lstm_rec_kernel,
                         cudaFuncAttributeMaxDynamicSharedMemorySize, 83200);

    dim3 ggrid(M_TOT / 64, G4 / 64, 2);
    gemm_xw_kernel<<<ggrid, 256>>>(x, Wihf, Wihb, bihf, bhhf, bihb, bhhb);

    lstm_rec_kernel<<<2 * NBPD, 256, 83200>>>(mask, Whhf, Whhb, out);
}

// round 8
// speedup vs baseline: 1.0238x; 1.0238x over previous
#include <cuda_runtime.h>
#include <cstddef>

#define L_SEQ 512
#define B_SZ  64
#define D_IN  512
#define HALFH 256
#define G4    1024                 // 4*HALF gate rows per direction
#define M_TOT (L_SEQ * B_SZ)      // 32768
#define NBPD  64                  // blocks per direction in recurrence
#define HB    4                   // hidden units per block

typedef unsigned long long u64;

// ---------------------------------------------------------------------------
// Packed fp32x2 helpers (sm_100+). IEEE fp32 per lane -> bit-identical math.
// ---------------------------------------------------------------------------
__device__ __forceinline__ u64 f2_dup(float v) {
    u64 r; asm("mov.b64 %0, {%1, %1};" : "=l"(r) : "f"(v)); return r;
}
__device__ __forceinline__ void f2_unpack(u64 p, float& lo, float& hi) {
    asm("mov.b64 {%0, %1}, %2;" : "=f"(lo), "=f"(hi) : "l"(p));
}
__device__ __forceinline__ u64 f2_fma(u64 a, u64 b, u64 c) {
    u64 d; asm("fma.rn.f32x2 %0, %1, %2, %3;" : "=l"(d) : "l"(a), "l"(b), "l"(c));
    return d;
}

// Morally-strong gpu-scope acquire/release on u32 (bypass L1, no IVALL).
__device__ __forceinline__ unsigned ld_acq(const unsigned* p) {
    unsigned v;
    asm volatile("ld.acquire.gpu.global.u32 %0, [%1];" : "=r"(v) : "l"(p) : "memory");
    return v;
}
__device__ __forceinline__ void st_rel(unsigned* p, unsigned v) {
    asm volatile("st.release.gpu.global.u32 [%0], %1;" :: "l"(p), "r"(v) : "memory");
}

// Scratch: xw[dir][g][m] with m = l*B + b   (256 MB, module-static: allowed)
__device__ float g_xw[(size_t)2 * G4 * M_TOT];
// Double-buffered hidden state: [dir][buf][b][k]
__device__ float g_h[2][2][B_SZ][HALFH];
// Flag barrier state: per-block flags (32B stride, no contention) + gen word.
__device__ unsigned g_flag[2][NBPD * 8];
__device__ unsigned g_gen[2][32];          // [dir][0], padded to separate lines

// ---------------------------------------------------------------------------
// Kernel 1: xw[dir][g][m] = sum_d W_ih[g][d] * x[m][d] + b_ih[g] + b_hh[g]
// Tiles: 64(g) x 64(m) x 16(k), 256 threads, 4x4 register tile, FFMA2 math.
// (unchanged this round -- isolate the barrier change)
// ---------------------------------------------------------------------------
__global__ __launch_bounds__(256) void gemm_xw_kernel(
    const float* __restrict__ x,
    const float* __restrict__ Wf, const float* __restrict__ Wb,
    const float* __restrict__ bihf, const float* __restrict__ bhhf,
    const float* __restrict__ bihb, const float* __restrict__ bhhb)
{
    const int dir = blockIdx.z;
    const float* __restrict__ W   = dir ? Wb   : Wf;
    const float* __restrict__ bih = dir ? bihb : bihf;
    const float* __restrict__ bhh = dir ? bhhb : bhhf;

    const int m0 = blockIdx.x * 64;
    const int g0 = blockIdx.y * 64;

    __shared__ float As[16][68];   // As[k][g']  (transposed stage; 272B row = 16B-aligned)
    __shared__ float Bs[16][68];   // Bs[k][m']

    const int tid = threadIdx.x;
    const int tx  = tid & 15;      // m sub-tile
    const int ty  = tid >> 4;      // g sub-tile

    const int lrow = tid >> 2;          // 0..63 (tile row to load)
    const int lc   = (tid & 3) * 4;     // k offset 0,4,8,12

    const float* Arow = W + (size_t)(g0 + lrow) * D_IN + lc;
    const float* Brow = x + (size_t)(m0 + lrow) * D_IN + lc;

    u64 acc2[4][2] = {};

    for (int k0 = 0; k0 < D_IN; k0 += 16) {
        float4 av = *(const float4*)(Arow + k0);
        float4 bv = *(const float4*)(Brow + k0);
        __syncthreads();
        As[lc + 0][lrow] = av.x; As[lc + 1][lrow] = av.y;
        As[lc + 2][lrow] = av.z; As[lc + 3][lrow] = av.w;
        Bs[lc + 0][lrow] = bv.x; Bs[lc + 1][lrow] = bv.y;
        Bs[lc + 2][lrow] = bv.z; Bs[lc + 3][lrow] = bv.w;
        __syncthreads();
#pragma unroll
        for (int kk = 0; kk < 16; kk++) {
            float4     a  = *(const float4*)&As[kk][ty * 4];     // warp-broadcast
            ulonglong2 bp = *(const ulonglong2*)&Bs[kk][tx * 4]; // conflict-free phases
            u64 d0 = f2_dup(a.x), d1 = f2_dup(a.y),
                d2 = f2_dup(a.z), d3 = f2_dup(a.w);
            acc2[0][0] = f2_fma(d0, bp.x, acc2[0][0]);
            acc2[0][1] = f2_fma(d0, bp.y, acc2[0][1]);
            acc2[1][0] = f2_fma(d1, bp.x, acc2[1][0]);
            acc2[1][1] = f2_fma(d1, bp.y, acc2[1][1]);
            acc2[2][0] = f2_fma(d2, bp.x, acc2[2][0]);
            acc2[2][1] = f2_fma(d2, bp.y, acc2[2][1]);
            acc2[3][0] = f2_fma(d3, bp.x, acc2[3][0]);
            acc2[3][1] = f2_fma(d3, bp.y, acc2[3][1]);
        }
    }

#pragma unroll
    for (int i = 0; i < 4; i++) {
        int g = g0 + ty * 4 + i;
        float bb = bih[g] + bhh[g];
        float c0, c1, c2, c3;
        f2_unpack(acc2[i][0], c0, c1);
        f2_unpack(acc2[i][1], c2, c3);
        float4 o;
        o.x = c0 + bb; o.y = c1 + bb; o.z = c2 + bb; o.w = c3 + bb;
        size_t base = ((size_t)dir * G4 + g) * M_TOT + m0 + tx * 4;
        *(float4*)&g_xw[base] = o;
    }
}

// ---------------------------------------------------------------------------
// Contention-free flag barrier over the NBPD blocks of one direction.
// Arrival: one st.release.gpu to a per-block 32B-padded flag (distinct
// addresses -> parallel, no atomics, no read/atomic line mixing).
// Leader block (blk_local 0): threads 0..NBPD-1 each acquire-spin on one flag,
// bar.sync (block-wide HB), tid0 release-stores gen = target.
// Others: tid0 acquire-spins gen, bar.sync.
// Visibility chain: writer h -> release flag -> leader acquire -> bar HB ->
// release gen -> reader acquire -> bar HB -> reader __ldcg h (L2 = coherence
// point; no L1 flush needed anywhere).
// target is monotonic across graph replays (base read from gen at start).
// ---------------------------------------------------------------------------
__device__ __forceinline__ void flag_barrier(int dir, int blk_local,
                                             unsigned target, int tid)
{
    __syncthreads();                            // block's h writes done
    if (tid == 0)
        st_rel(&g_flag[dir][blk_local * 8], target);
    if (blk_local == 0) {
        if (tid < NBPD) {
            unsigned v;
            do { v = ld_acq(&g_flag[dir][tid * 8]); }
            while ((int)(v - target) < 0);
        }
        __syncthreads();
        if (tid == 0)
            st_rel(&g_gen[dir][0], target);
    } else {
        if (tid == 0) {
            unsigned v;
            do { v = ld_acq(&g_gen[dir][0]); }
            while ((int)(v - target) < 0);
        }
        __syncthreads();
    }
}

// ---------------------------------------------------------------------------
// Kernel 2: persistent bidirectional LSTM recurrence.
// Grid = 128 blocks (0..63 fwd, 64..127 bwd), 256 threads each.
// 128 blocks <= 148 SMs -> whole grid co-resident in wave 1 (no deadlock).
// Block owns HB=4 hidden units; thread (b,q) computes all 4 gates of its cell.
// W_p PAIR-INTERLEAVED per hidden unit ((i,f) pair / (g,o) pair).
// h staging via __ldcg (L2): 16 front-batched LDG.128 then 16 STS.128.
// xw seeds via __ldcs (streaming), consumed after the dot loop.
// Dynamic SMEM: h_s[64][260] + W_p[8][520] = 83200 B (1 CTA/SM)
// ---------------------------------------------------------------------------
__global__ __launch_bounds__(256, 1) void lstm_rec_kernel(
    const float* __restrict__ mask,
    const float* __restrict__ Whhf, const float* __restrict__ Whhb,
    float* __restrict__ out)
{
    extern __shared__ float smem[];
    float (*h_s)[260] = (float(*)[260])smem;                     // 64 x 260
    float (*W_p)[520] = (float(*)[520])(smem + 64 * 260);        // 8  x 520

    const int blk = blockIdx.x;
    const int dir = blk >> 6;
    const int blk_local = blk & 63;
    const int j0  = blk_local * HB;
    const float* __restrict__ Whh = dir ? Whhb : Whhf;

    const int tid = threadIdx.x;
    const int b   = tid & 63;     // batch lane
    const int q   = tid >> 6;     // local hidden unit owned by this thread

    // Monotonic barrier base from previous launch (all threads read same).
    const unsigned base = ld_acq(&g_gen[dir][0]);

    // Load W slice pair-interleaved BY HIDDEN UNIT:
    //   local row r = jj*4 + gt  <-  Whh[gt*HALF + j0 + jj][:]
    //   pair pr = jj*2 + (gt>>1), slot = gt&1;  W_p[pr][2*k + slot] = row[k]
    for (int idx = tid; idx < 16 * 64; idx += 256) {
        int r = idx >> 6, kq = idx & 63;
        int jj = r >> 2, gt = r & 3;
        float4 w4 = *(const float4*)&Whh[(size_t)(gt * HALFH + j0 + jj) * HALFH + kq * 4];
        int pr = jj * 2 + (gt >> 1), slot = gt & 1, kb = kq * 4;
        W_p[pr][2 * (kb + 0) + slot] = w4.x;
        W_p[pr][2 * (kb + 1) + slot] = w4.y;
        W_p[pr][2 * (kb + 2) + slot] = w4.z;
        W_p[pr][2 * (kb + 3) + slot] = w4.w;
    }

    // Zero our slice of the step-0 read buffer; c lives in a register.
    g_h[dir][0][b][j0 + q] = 0.0f;
    float c = 0.0f;

    flag_barrier(dir, blk_local, base + 1, tid);   // zeros visible to all

    const float* __restrict__ WpIF = &W_p[2 * q + 0][0];   // gates (i,f)
    const float* __restrict__ WpGO = &W_p[2 * q + 1][0];   // gates (g,o)

    // Strength-reduced stream pointers (stride +/-B_SZ per step).
    const int t0 = dir ? (L_SEQ - 1) : 0;
    const ptrdiff_t dstep = dir ? -(ptrdiff_t)B_SZ : (ptrdiff_t)B_SZ;
    const float* __restrict__ xwb =
        g_xw + (size_t)dir * G4 * M_TOT + (size_t)t0 * B_SZ + b;
    const float* pi = xwb + (size_t)(0 * HALFH + j0 + q) * M_TOT;
    const float* pf = xwb + (size_t)(1 * HALFH + j0 + q) * M_TOT;
    const float* pg = xwb + (size_t)(2 * HALFH + j0 + q) * M_TOT;
    const float* po = xwb + (size_t)(3 * HALFH + j0 + q) * M_TOT;
    const float* pm = mask + (size_t)t0 * B_SZ + b;
    float* pout = out + ((size_t)t0 * B_SZ + b) * 512 + dir * HALFH + j0 + q;
    const ptrdiff_t dout = dstep * 512;

    // Staging: thread covers rows bb = (tid>>6) + {0,4,...,60} at column
    // block kq = (tid & 63)*4; one float4 per row -> 16 LDG.128 + 16 STS.128.
    const int st_b0 = tid >> 6;          // 0..3
    const int st_kq = (tid & 63) * 4;    // 0..252
    const float* hsrc0 = &g_h[dir][0][0][0] + (size_t)st_b0 * HALFH + st_kq;
    const size_t hbufoff = (size_t)B_SZ * HALFH;   // floats between buf0/buf1
    float* hdst1 = &g_h[dir][1][0][0] + (size_t)b * HALFH + j0 + q;
    float* hwr[2] = { hdst1 - hbufoff, hdst1 };    // write ptr per target buf

    int rbuf = 0;

    for (int s = 0; s < L_SEQ; s++) {
        // Seed + mask loads issue early; consumed only AFTER the dot loop.
        float ai = __ldcs(pi), af = __ldcs(pf), ag = __ldcs(pg), ao = __ldcs(po);
        float mv = *pm;

        // Stage full h (64x256) from L2 (ldcg: coherent, bypasses stale L1).
        {
            const float* src = hsrc0 + (size_t)rbuf * hbufoff;
            float4 r[16];
#pragma unroll
            for (int i = 0; i < 16; i++)
                r[i] = __ldcg((const float4*)(src + (size_t)(i * 4) * HALFH));
#pragma unroll
            for (int i = 0; i < 16; i++)
                *(float4*)&h_s[st_b0 + i * 4][st_kq] = r[i];
        }
        __syncthreads();

        u64 accIF = 0;   // packed (0.0f, 0.0f)
        u64 accGO = 0;

        // gates(i,f,g,o)[b, j0+q] += sum_k h[b][k] * W[row][k]
        // Per 4 k: 1 h LDS.128 (conflict-free: stride 260 = 4 mod 32) +
        //          4 W LDS.128 (warp-broadcast) + 4 dup movs + 8 FFMA2
#pragma unroll 8
        for (int k = 0; k < HALFH; k += 4) {
            float4 h4 = *(const float4*)&h_s[b][k];
            ulonglong2 wi0 = *(const ulonglong2*)&WpIF[2 * k];     // k, k+1
            ulonglong2 wi1 = *(const ulonglong2*)&WpIF[2 * k + 4]; // k+2, k+3
            ulonglong2 wg0 = *(const ulonglong2*)&WpGO[2 * k];
            ulonglong2 wg1 = *(const ulonglong2*)&WpGO[2 * k + 4];
            u64 hx = f2_dup(h4.x), hy = f2_dup(h4.y),
                hz = f2_dup(h4.z), hw = f2_dup(h4.w);
            accIF = f2_fma(hx, wi0.x, accIF);
            accIF = f2_fma(hy, wi0.y, accIF);
            accIF = f2_fma(hz, wi1.x, accIF);
            accIF = f2_fma(hw, wi1.y, accIF);
            accGO = f2_fma(hx, wg0.x, accGO);
            accGO = f2_fma(hy, wg0.y, accGO);
            accGO = f2_fma(hz, wg1.x, accGO);
            accGO = f2_fma(hw, wg1.y, accGO);
        }

        // Cell update: add seeds now (their latency is long hidden).
        float di, df, dg, dgo;
        f2_unpack(accIF, di, df);
        f2_unpack(accGO, dg, dgo);
        float gi = di + ai, gf = df + af, gg = dg + ag, go = dgo + ao;
        float si = 1.0f / (1.0f + __expf(-gi));
        float sf = 1.0f / (1.0f + __expf(-gf));
        float so = 1.0f / (1.0f + __expf(-go));
        c = sf * c + si * tanhf(gg);
        float h = so * tanhf(c);
        h *= mv;
        c *= mv;

        hwr[rbuf ^ 1][0] = h;   // write h to the other buffer (plain STG -> L2)
        *pout = h;

        flag_barrier(dir, blk_local, base + 2 + s, tid);  // all blocks step
        rbuf ^= 1;
        pi += dstep; pf += dstep; pg += dstep; po += dstep;
        pm += dstep; pout += dout;
    }
}

// ---------------------------------------------------------------------------
// Launch
// d_in: 0=x 1=mask 2=W_ih_f 3=W_hh_f 4=b_ih_f 5=b_hh_f 6=W_ih_b 7=W_hh_b 8=b_ih_b 9=b_hh_b
// ---------------------------------------------------------------------------
extern "C" void kernel_launch(void* const* d_in, const int* in_sizes, int n_in,
                              void* d_out, int out_size)
{
    const float* x     = (const float*)d_in[0];
    const float* mask  = (const float*)d_in[1];
    const float* Wihf  = (const float*)d_in[2];
    const float* Whhf  = (const float*)d_in[3];
    const float* bihf  = (const float*)d_in[4];
    const float* bhhf  = (const float*)d_in[5];
    const float* Wihb  = (const float*)d_in[6];
    const float* Whhb  = (const float*)d_in[7];
    const float* bihb  = (const float*)d_in[8];
    const float* bhhb  = (const float*)d_in[9];
    float* out = (float*)d_out;

    // Idempotent, deterministic; needed for 83 KB dynamic SMEM.
    cudaFuncSetAttribute(lstm_rec_kernel,
                         cudaFuncAttributeMaxDynamicSharedMemorySize, 83200);

    dim3 ggrid(M_TOT / 64, G4 / 64, 2);
    gemm_xw_kernel<<<ggrid, 256>>>(x, Wihf, Wihb, bihf, bhhf, bihb, bhhb);

    lstm_rec_kernel<<<2 * NBPD, 256, 83200>>>(mask, Whhf, Whhb, out);
}